// round 16
// baseline (speedup 1.0000x reference)
#include <cuda_runtime.h>
#include <cuda_bf16.h>
#include <cstdint>

// Problem constants
#define BATCH 512
#define DD 512
#define NITER 6
#define SPLITK 4
#define KPER (DD / SPLITK)      // 128 per gemm CTA
#define BK 64                   // k-chunk staged in smem
#define APITCH 72               // padded smem pitch (bank-conflict-free ldmatrix)
#define HALF_ROWS 256
#define N_GEMM_HALF 128         // 8 bn x 4 bm x 4 kz

// ---------------------------------------------------------------------------
// Scratch (device globals — no allocation allowed)
// ---------------------------------------------------------------------------
__device__ float g_r[BATCH * DD];
__device__ float g_p[BATCH * DD];
__device__ float g_y[BATCH * DD];
__device__ float g_qp[SPLITK][BATCH * DD];
__device__ __nv_bfloat16 g_p_hi[BATCH * DD];
__device__ __nv_bfloat16 g_p_lo[BATCH * DD];
__device__ __nv_bfloat16 g_c_hi[DD * DD];
__device__ __nv_bfloat16 g_c_lo[DD * DD];
__device__ float g_shift[BATCH];
__device__ float g_oscale[BATCH];
__device__ float g_rr[BATCH];

// ---------------------------------------------------------------------------
// PTX helpers (sm_80-era instructions only — safe for plain sm_103 ptxas)
// ---------------------------------------------------------------------------
__device__ __forceinline__ uint32_t smem_u32(const void* p) {
    uint32_t a;
    asm("{ .reg .u64 t; cvta.to.shared.u64 t, %1; cvt.u32.u64 %0, t; }"
        : "=r"(a) : "l"(p));
    return a;
}

__device__ __forceinline__ void ldsm4(uint32_t* r, uint32_t addr) {
    asm volatile("ldmatrix.sync.aligned.m8n8.x4.shared.b16 {%0,%1,%2,%3}, [%4];"
                 : "=r"(r[0]), "=r"(r[1]), "=r"(r[2]), "=r"(r[3]) : "r"(addr));
}

__device__ __forceinline__ void mma_bf16(float* d, const uint32_t* a,
                                         uint32_t b0, uint32_t b1) {
    asm volatile(
        "mma.sync.aligned.m16n8k16.row.col.f32.bf16.bf16.f32 "
        "{%0,%1,%2,%3}, {%4,%5,%6,%7}, {%8,%9}, {%0,%1,%2,%3};"
        : "+f"(d[0]), "+f"(d[1]), "+f"(d[2]), "+f"(d[3])
        : "r"(a[0]), "r"(a[1]), "r"(a[2]), "r"(a[3]), "r"(b0), "r"(b1));
}

__device__ __forceinline__ float warp_sum(float v) {
#pragma unroll
    for (int m = 16; m > 0; m >>= 1)
        v += __shfl_xor_sync(0xFFFFFFFFu, v, m);
    return v;
}

// ---------------------------------------------------------------------------
// Init (warp-per-row, zero barriers)
// ---------------------------------------------------------------------------
__global__ __launch_bounds__(256) void init_kernel(const float* __restrict__ x,
                                                   const float* __restrict__ t,
                                                   const float* __restrict__ mu) {
    const int lane = threadIdx.x & 31;
    const int b = blockIdx.x * 8 + (threadIdx.x >> 5);
    float tv = t[b];
    float B = 9.95f * tv * tv + 0.1f * tv;
    float eh = expf(0.5f * B);
    if (lane == 0) {
        g_shift[b] = expm1f(B);
        g_oscale[b] = -(eh * sqrtf(-expm1f(-B)));
    }
    const int base = b * DD + lane * 4;
    float acc = 0.0f;
#pragma unroll
    for (int i = 0; i < 4; i++) {
        int idx = base + i * 128;
        float4 xv = *(const float4*)&x[idx];
        float4 mv = *(const float4*)&mu[lane * 4 + i * 128];
        float4 v;
        v.x = eh * xv.x - mv.x;
        v.y = eh * xv.y - mv.y;
        v.z = eh * xv.z - mv.z;
        v.w = eh * xv.w - mv.w;
        *(float4*)&g_r[idx] = v;
        *(float4*)&g_p[idx] = v;
        *(float4*)&g_y[idx] = make_float4(0.f, 0.f, 0.f, 0.f);
        __nv_bfloat162 h01, h23, l01, l23;
        h01.x = __float2bfloat16(v.x); h01.y = __float2bfloat16(v.y);
        h23.x = __float2bfloat16(v.z); h23.y = __float2bfloat16(v.w);
        l01.x = __float2bfloat16(v.x - __bfloat162float(h01.x));
        l01.y = __float2bfloat16(v.y - __bfloat162float(h01.y));
        l23.x = __float2bfloat16(v.z - __bfloat162float(h23.x));
        l23.y = __float2bfloat16(v.w - __bfloat162float(h23.y));
        *(__nv_bfloat162*)&g_p_hi[idx] = h01;
        *(__nv_bfloat162*)&g_p_hi[idx + 2] = h23;
        *(__nv_bfloat162*)&g_p_lo[idx] = l01;
        *(__nv_bfloat162*)&g_p_lo[idx + 2] = l23;
        acc += v.x * v.x + v.y * v.y + v.z * v.z + v.w * v.w;
    }
    acc = warp_sum(acc);
    if (lane == 0) g_rr[b] = acc;
}

// ---------------------------------------------------------------------------
// Prep C: bf16 hi/lo split of posterior_cov (symmetric: row n == col n)
// ---------------------------------------------------------------------------
__global__ __launch_bounds__(256) void prep_c_kernel(const float* __restrict__ cov) {
    int i = blockIdx.x;
    int tid = threadIdx.x;
#pragma unroll
    for (int k = 0; k < 2; k++) {
        int idx = i * DD + tid + k * 256;
        float v = cov[idx];
        __nv_bfloat16 h = __float2bfloat16(v);
        g_c_hi[idx] = h;
        g_c_lo[idx] = __float2bfloat16(v - __bfloat162float(h));
    }
}

// ---------------------------------------------------------------------------
// COMBO kernel: blocks [0, n_gemm) run the validated mma.sync GEMM for one
// batch-half; blocks [n_gemm, n_gemm+256) run the validated two-phase CG
// update for the OTHER half (disjoint rows — no races; the dependency
// between G(h,i) and C(h,i) is carried by the previous combo launch).
// ---------------------------------------------------------------------------
__global__ __launch_bounds__(128) void combo_kernel(int n_gemm, int gemm_base,
                                                    int cg_base, int cg_last,
                                                    float* __restrict__ out) {
    __shared__ __nv_bfloat16 sAhi[64][APITCH];
    __shared__ __nv_bfloat16 sAlo[64][APITCH];
    __shared__ __nv_bfloat16 sBhi[64][APITCH];
    __shared__ __nv_bfloat16 sBlo[64][APITCH];
    __shared__ float sdot[4];
    __shared__ float srr[4];

    const int tid = threadIdx.x;
    const int lid = tid & 31;
    const int wid = tid >> 5;

    if ((int)blockIdx.x < n_gemm) {
        // ================= GEMM path (validated R15 body) =================
        const int bid = blockIdx.x;
        const int bn = (bid & 7) * 64;
        const int bm = gemm_base + ((bid >> 3) & 3) * 64;
        const int kbase = (bid >> 5) * KPER;
        const int wm = (wid & 1) * 32;
        const int wn = (wid >> 1) * 32;

        float acc[2][4][4];
#pragma unroll
        for (int i = 0; i < 2; i++)
#pragma unroll
            for (int j = 0; j < 4; j++)
#pragma unroll
                for (int v = 0; v < 4; v++) acc[i][j][v] = 0.0f;

        const int lrow = lid & 15;
        const int lcol8 = (lid >> 4) * 8;

        for (int kc = kbase; kc < kbase + KPER; kc += BK) {
            __syncthreads();
#pragma unroll
            for (int i = 0; i < 4; i++) {
                int slot = tid + 128 * i;
                int row = slot >> 3;
                int c8 = (slot & 7) * 8;
                *(uint4*)&sAhi[row][c8] = *(const uint4*)&g_p_hi[(bm + row) * DD + kc + c8];
                *(uint4*)&sAlo[row][c8] = *(const uint4*)&g_p_lo[(bm + row) * DD + kc + c8];
                *(uint4*)&sBhi[row][c8] = *(const uint4*)&g_c_hi[(bn + row) * DD + kc + c8];
                *(uint4*)&sBlo[row][c8] = *(const uint4*)&g_c_lo[(bn + row) * DD + kc + c8];
            }
            __syncthreads();

#pragma unroll
            for (int ks = 0; ks < BK / 16; ks++) {
                int kk = ks * 16 + lcol8;
                uint32_t ahi[2][4], alo[2][4], bhi[2][4], blo[2][4];
#pragma unroll
                for (int mi = 0; mi < 2; mi++) {
                    ldsm4(ahi[mi], smem_u32(&sAhi[wm + mi * 16 + lrow][kk]));
                    ldsm4(alo[mi], smem_u32(&sAlo[wm + mi * 16 + lrow][kk]));
                }
#pragma unroll
                for (int nh = 0; nh < 2; nh++) {
                    ldsm4(bhi[nh], smem_u32(&sBhi[wn + nh * 16 + lrow][kk]));
                    ldsm4(blo[nh], smem_u32(&sBlo[wn + nh * 16 + lrow][kk]));
                }
#pragma unroll
                for (int mi = 0; mi < 2; mi++)
#pragma unroll
                    for (int ni = 0; ni < 4; ni++) {
                        int nh = ni >> 1, sb = ni & 1;
                        mma_bf16(acc[mi][ni], ahi[mi], bhi[nh][sb], bhi[nh][sb + 2]);
                        mma_bf16(acc[mi][ni], ahi[mi], blo[nh][sb], blo[nh][sb + 2]);
                        mma_bf16(acc[mi][ni], alo[mi], bhi[nh][sb], bhi[nh][sb + 2]);
                    }
            }
        }

        float* qp = g_qp[bid >> 5];
        const int g = lid >> 2, tq = lid & 3;
#pragma unroll
        for (int mi = 0; mi < 2; mi++)
#pragma unroll
            for (int ni = 0; ni < 4; ni++) {
                int row = bm + wm + mi * 16 + g;
                int col = bn + wn + ni * 8 + tq * 2;
                *(float2*)&qp[row * DD + col] = make_float2(acc[mi][ni][0], acc[mi][ni][1]);
                *(float2*)&qp[(row + 8) * DD + col] = make_float2(acc[mi][ni][2], acc[mi][ni][3]);
            }
    } else {
        // ================= CG path (validated R15 two-phase body) =========
        const int b = cg_base + ((int)blockIdx.x - n_gemm);
        const int w = wid;
        const float sh = g_shift[b];
        const float rro = g_rr[b];
        const int idx = b * DD + tid * 4;

        float4 p = *(const float4*)&g_p[idx];
        float4 qa = *(const float4*)&g_qp[0][idx];
        float4 qb = *(const float4*)&g_qp[1][idx];
        float4 qc = *(const float4*)&g_qp[2][idx];
        float4 qd = *(const float4*)&g_qp[3][idx];
        float4 q;
        q.x = (qa.x + qb.x) + (qc.x + qd.x) + sh * p.x;
        q.y = (qa.y + qb.y) + (qc.y + qd.y) + sh * p.y;
        q.z = (qa.z + qb.z) + (qc.z + qd.z) + sh * p.z;
        q.w = (qa.w + qb.w) + (qc.w + qd.w) + sh * p.w;
        float4 y = *(const float4*)&g_y[idx];
        float4 r;
        if (!cg_last) r = *(const float4*)&g_r[idx];

        float dot = p.x * q.x + p.y * q.y + p.z * q.z + p.w * q.w;
        dot = warp_sum(dot);
        if (lid == 0) sdot[w] = dot;
        __syncthreads();
        float alpha = rro / fmaxf((sdot[0] + sdot[1]) + (sdot[2] + sdot[3]), 1e-30f);

        if (cg_last) {
            float os = g_oscale[b];
            float4 o;
            o.x = os * (y.x + alpha * p.x);
            o.y = os * (y.y + alpha * p.y);
            o.z = os * (y.z + alpha * p.z);
            o.w = os * (y.w + alpha * p.w);
            *(float4*)&out[idx] = o;
            return;
        }

        y.x += alpha * p.x; y.y += alpha * p.y;
        y.z += alpha * p.z; y.w += alpha * p.w;
        *(float4*)&g_y[idx] = y;
        r.x -= alpha * q.x; r.y -= alpha * q.y;
        r.z -= alpha * q.z; r.w -= alpha * q.w;
        *(float4*)&g_r[idx] = r;

        float rr_new = r.x * r.x + r.y * r.y + r.z * r.z + r.w * r.w;
        rr_new = warp_sum(rr_new);
        if (lid == 0) srr[w] = rr_new;
        __syncthreads();
        rr_new = (srr[0] + srr[1]) + (srr[2] + srr[3]);
        float beta = rr_new / fmaxf(rro, 1e-30f);
        if (tid == 0) g_rr[b] = rr_new;

        float4 pn;
        pn.x = r.x + beta * p.x;
        pn.y = r.y + beta * p.y;
        pn.z = r.z + beta * p.z;
        pn.w = r.w + beta * p.w;
        *(float4*)&g_p[idx] = pn;

        __nv_bfloat162 h01, h23, l01, l23;
        h01.x = __float2bfloat16(pn.x);
        h01.y = __float2bfloat16(pn.y);
        h23.x = __float2bfloat16(pn.z);
        h23.y = __float2bfloat16(pn.w);
        l01.x = __float2bfloat16(pn.x - __bfloat162float(h01.x));
        l01.y = __float2bfloat16(pn.y - __bfloat162float(h01.y));
        l23.x = __float2bfloat16(pn.z - __bfloat162float(h23.x));
        l23.y = __float2bfloat16(pn.w - __bfloat162float(h23.y));
        *(__nv_bfloat162*)&g_p_hi[idx] = h01;
        *(__nv_bfloat162*)&g_p_hi[idx + 2] = h23;
        *(__nv_bfloat162*)&g_p_lo[idx] = l01;
        *(__nv_bfloat162*)&g_p_lo[idx + 2] = l23;
    }
}

// ---------------------------------------------------------------------------
// Pipelined schedule over two independent halves A(rows 0-255), B(256-511):
//   k=0:  G(A,0)
//   k=2i+1: G(B,i) + C(A,i)        (i = 0..5)
//   k=2i+2: G(A,i+1) + C(B,i)      (i = 0..4)  [k even >= 2]
//   k=12: C(B,5)  (LAST)
// Deps all carried by launch boundaries; within a combo, halves are disjoint.
// ---------------------------------------------------------------------------
extern "C" void kernel_launch(void* const* d_in, const int* in_sizes, int n_in,
                              void* d_out, int out_size) {
    const float* x = (const float*)d_in[0];
    const float* t = (const float*)d_in[1];
    const float* mu = (const float*)d_in[2];
    const float* cov = (const float*)d_in[3];
    float* out = (float*)d_out;

    init_kernel<<<BATCH / 8, 256>>>(x, t, mu);
    prep_c_kernel<<<DD, 256>>>(cov);

    for (int k = 0; k <= 12; k++) {
        int has_gemm = (k <= 11);
        int has_cg = (k >= 1);
        int n_gemm = has_gemm ? N_GEMM_HALF : 0;
        int gemm_base = (k & 1) * HALF_ROWS;         // G half: even k -> A, odd -> B
        int cg_base = (k & 1) ? 0 : HALF_ROWS;       // C half: odd k -> A, even -> B
        int cg_iter = (k & 1) ? (k - 1) / 2 : (k - 2) / 2;
        int cg_last = (cg_iter == NITER - 1) ? 1 : 0;
        int n_cg = has_cg ? HALF_ROWS : 0;
        combo_kernel<<<n_gemm + n_cg, 128>>>(n_gemm, gemm_base, cg_base,
                                             cg_last, out);
    }
}

// round 17
// speedup vs baseline: 1.3973x; 1.3973x over previous
#include <cuda_runtime.h>
#include <cuda_bf16.h>
#include <cstdint>

// Problem constants
#define BATCH 512
#define DD 512
#define NITER 6
#define SPLITK 4
#define KPER (DD / SPLITK)      // 128 per gemm CTA (fully staged in smem)
#define APITCH 136              // padded smem pitch (136 mod 64 == 8: conflict-free)

// ---------------------------------------------------------------------------
// Scratch (device globals — no allocation allowed)
// ---------------------------------------------------------------------------
__device__ float g_r[BATCH * DD];
__device__ float g_p[BATCH * DD];
__device__ float g_y[BATCH * DD];
__device__ float g_qp[SPLITK][BATCH * DD];
__device__ __nv_bfloat16 g_p_hi[BATCH * DD];
__device__ __nv_bfloat16 g_p_lo[BATCH * DD];
__device__ __nv_bfloat16 g_c_hi[DD * DD];
__device__ __nv_bfloat16 g_c_lo[DD * DD];
__device__ float g_shift[BATCH];
__device__ float g_oscale[BATCH];
__device__ float g_rr[BATCH];

// ---------------------------------------------------------------------------
// PTX helpers (sm_80-era instructions only — safe for plain sm_103 ptxas)
// ---------------------------------------------------------------------------
__device__ __forceinline__ uint32_t smem_u32(const void* p) {
    uint32_t a;
    asm("{ .reg .u64 t; cvta.to.shared.u64 t, %1; cvt.u32.u64 %0, t; }"
        : "=r"(a) : "l"(p));
    return a;
}

__device__ __forceinline__ void ldsm4(uint32_t* r, uint32_t addr) {
    asm volatile("ldmatrix.sync.aligned.m8n8.x4.shared.b16 {%0,%1,%2,%3}, [%4];"
                 : "=r"(r[0]), "=r"(r[1]), "=r"(r[2]), "=r"(r[3]) : "r"(addr));
}

__device__ __forceinline__ void mma_bf16(float* d, const uint32_t* a,
                                         uint32_t b0, uint32_t b1) {
    asm volatile(
        "mma.sync.aligned.m16n8k16.row.col.f32.bf16.bf16.f32 "
        "{%0,%1,%2,%3}, {%4,%5,%6,%7}, {%8,%9}, {%0,%1,%2,%3};"
        : "+f"(d[0]), "+f"(d[1]), "+f"(d[2]), "+f"(d[3])
        : "r"(a[0]), "r"(a[1]), "r"(a[2]), "r"(a[3]), "r"(b0), "r"(b1));
}

__device__ __forceinline__ float warp_sum(float v) {
#pragma unroll
    for (int m = 16; m > 0; m >>= 1)
        v += __shfl_xor_sync(0xFFFFFFFFu, v, m);
    return v;
}

// ---------------------------------------------------------------------------
// Fused setup: blocks [0,64) = init (warp-per-row rhs/scalars/splits);
// blocks [64,576) = prep_c row (bf16 hi/lo split of symmetric cov).
// Both paths are register-light — no R16-style worst-case-union tax.
// ---------------------------------------------------------------------------
__global__ __launch_bounds__(256) void setup_kernel(const float* __restrict__ x,
                                                    const float* __restrict__ t,
                                                    const float* __restrict__ mu,
                                                    const float* __restrict__ cov) {
    if (blockIdx.x < 64) {
        const int lane = threadIdx.x & 31;
        const int b = blockIdx.x * 8 + (threadIdx.x >> 5);
        float tv = t[b];
        float B = 9.95f * tv * tv + 0.1f * tv;
        float eh = expf(0.5f * B);
        if (lane == 0) {
            g_shift[b] = expm1f(B);
            g_oscale[b] = -(eh * sqrtf(-expm1f(-B)));
        }
        const int base = b * DD + lane * 4;
        float acc = 0.0f;
#pragma unroll
        for (int i = 0; i < 4; i++) {
            int idx = base + i * 128;
            float4 xv = *(const float4*)&x[idx];
            float4 mv = *(const float4*)&mu[lane * 4 + i * 128];
            float4 v;
            v.x = eh * xv.x - mv.x;
            v.y = eh * xv.y - mv.y;
            v.z = eh * xv.z - mv.z;
            v.w = eh * xv.w - mv.w;
            *(float4*)&g_r[idx] = v;
            *(float4*)&g_p[idx] = v;
            *(float4*)&g_y[idx] = make_float4(0.f, 0.f, 0.f, 0.f);
            __nv_bfloat162 h01, h23, l01, l23;
            h01.x = __float2bfloat16(v.x); h01.y = __float2bfloat16(v.y);
            h23.x = __float2bfloat16(v.z); h23.y = __float2bfloat16(v.w);
            l01.x = __float2bfloat16(v.x - __bfloat162float(h01.x));
            l01.y = __float2bfloat16(v.y - __bfloat162float(h01.y));
            l23.x = __float2bfloat16(v.z - __bfloat162float(h23.x));
            l23.y = __float2bfloat16(v.w - __bfloat162float(h23.y));
            *(__nv_bfloat162*)&g_p_hi[idx] = h01;
            *(__nv_bfloat162*)&g_p_hi[idx + 2] = h23;
            *(__nv_bfloat162*)&g_p_lo[idx] = l01;
            *(__nv_bfloat162*)&g_p_lo[idx + 2] = l23;
            acc += v.x * v.x + v.y * v.y + v.z * v.z + v.w * v.w;
        }
        acc = warp_sum(acc);
        if (lane == 0) g_rr[b] = acc;
    } else {
        const int i = blockIdx.x - 64;
        const int tid = threadIdx.x;
#pragma unroll
        for (int k = 0; k < 2; k++) {
            int idx = i * DD + tid + k * 256;
            float v = cov[idx];
            __nv_bfloat16 h = __float2bfloat16(v);
            g_c_hi[idx] = h;
            g_c_lo[idx] = __float2bfloat16(v - __bfloat162float(h));
        }
    }
}

// ---------------------------------------------------------------------------
// mma.sync GEMM, single-stage: full K-slice (KPER=128) staged once in
// dynamic smem (~70 KB), ONE load phase (32 uint4/thread, high MLP),
// 2 barriers total, then 8 unrolled K-steps. Accumulation order per
// kz-slice identical to the validated two-chunk version.
// Grid (8, 8, 4) = 256 CTAs.
// ---------------------------------------------------------------------------
#define TILE_ELEMS (64 * APITCH)

__global__ __launch_bounds__(128) void gemm_mma_kernel() {
    extern __shared__ __align__(16) __nv_bfloat16 smem[];
    __nv_bfloat16* sAhi = smem;
    __nv_bfloat16* sAlo = smem + TILE_ELEMS;
    __nv_bfloat16* sBhi = smem + 2 * TILE_ELEMS;
    __nv_bfloat16* sBlo = smem + 3 * TILE_ELEMS;

    const int tid = threadIdx.x;
    const int lid = tid & 31;
    const int wid = tid >> 5;
    const int wm = (wid & 1) * 32;
    const int wn = (wid >> 1) * 32;
    const int bm = blockIdx.y * 64;
    const int bn = blockIdx.x * 64;
    const int kbase = blockIdx.z * KPER;

    float acc[2][4][4];
#pragma unroll
    for (int i = 0; i < 2; i++)
#pragma unroll
        for (int j = 0; j < 4; j++)
#pragma unroll
            for (int v = 0; v < 4; v++) acc[i][j][v] = 0.0f;

    // Single load phase: 64 rows x 16 col-groups = 1024 uint4 slots per tile
#pragma unroll
    for (int i = 0; i < 8; i++) {
        int slot = tid + 128 * i;
        int row = slot >> 4;
        int c8 = (slot & 15) * 8;
        int goff = (bm + row) * DD + kbase + c8;
        int boff = (bn + row) * DD + kbase + c8;
        int soff = row * APITCH + c8;
        *(uint4*)&sAhi[soff] = *(const uint4*)&g_p_hi[goff];
        *(uint4*)&sAlo[soff] = *(const uint4*)&g_p_lo[goff];
        *(uint4*)&sBhi[soff] = *(const uint4*)&g_c_hi[boff];
        *(uint4*)&sBlo[soff] = *(const uint4*)&g_c_lo[boff];
    }
    __syncthreads();

    const int lrow = lid & 15;
    const int lcol8 = (lid >> 4) * 8;

#pragma unroll
    for (int ks = 0; ks < KPER / 16; ks++) {
        int kk = ks * 16 + lcol8;
        uint32_t ahi[2][4], alo[2][4], bhi[2][4], blo[2][4];
#pragma unroll
        for (int mi = 0; mi < 2; mi++) {
            ldsm4(ahi[mi], smem_u32(&sAhi[(wm + mi * 16 + lrow) * APITCH + kk]));
            ldsm4(alo[mi], smem_u32(&sAlo[(wm + mi * 16 + lrow) * APITCH + kk]));
        }
#pragma unroll
        for (int nh = 0; nh < 2; nh++) {
            ldsm4(bhi[nh], smem_u32(&sBhi[(wn + nh * 16 + lrow) * APITCH + kk]));
            ldsm4(blo[nh], smem_u32(&sBlo[(wn + nh * 16 + lrow) * APITCH + kk]));
        }
#pragma unroll
        for (int mi = 0; mi < 2; mi++)
#pragma unroll
            for (int ni = 0; ni < 4; ni++) {
                int nh = ni >> 1, sb = ni & 1;
                mma_bf16(acc[mi][ni], ahi[mi], bhi[nh][sb], bhi[nh][sb + 2]);
                mma_bf16(acc[mi][ni], ahi[mi], blo[nh][sb], blo[nh][sb + 2]);
                mma_bf16(acc[mi][ni], alo[mi], bhi[nh][sb], bhi[nh][sb + 2]);
            }
    }

    float* qp = g_qp[blockIdx.z];
    const int g = lid >> 2, tq = lid & 3;
#pragma unroll
    for (int mi = 0; mi < 2; mi++)
#pragma unroll
        for (int ni = 0; ni < 4; ni++) {
            int row = bm + wm + mi * 16 + g;
            int col = bn + wn + ni * 8 + tq * 2;
            *(float2*)&qp[row * DD + col] = make_float2(acc[mi][ni][0], acc[mi][ni][1]);
            *(float2*)&qp[(row + 8) * DD + col] = make_float2(acc[mi][ni][2], acc[mi][ni][3]);
        }
}

// ---------------------------------------------------------------------------
// CG update: TWO-phase reduction (validated R15 body, unchanged).
// 1 row per 128-thread block (512 blocks), 4 elems/thread, hoisted loads.
// LAST=true: out = oscale*(y + alpha*p) only.
// ---------------------------------------------------------------------------
template <bool LAST>
__global__ __launch_bounds__(128) void cg_update_kernel(float* __restrict__ out) {
    const int tid = threadIdx.x;
    const int w = tid >> 5;
    const int b = blockIdx.x;
    const float sh = g_shift[b];
    const float rro = g_rr[b];
    const int idx = b * DD + tid * 4;

    __shared__ float sdot[4];
    __shared__ float srr[4];

    float4 p = *(const float4*)&g_p[idx];
    float4 qa = *(const float4*)&g_qp[0][idx];
    float4 qb = *(const float4*)&g_qp[1][idx];
    float4 qc = *(const float4*)&g_qp[2][idx];
    float4 qd = *(const float4*)&g_qp[3][idx];
    float4 q;
    q.x = (qa.x + qb.x) + (qc.x + qd.x) + sh * p.x;
    q.y = (qa.y + qb.y) + (qc.y + qd.y) + sh * p.y;
    q.z = (qa.z + qb.z) + (qc.z + qd.z) + sh * p.z;
    q.w = (qa.w + qb.w) + (qc.w + qd.w) + sh * p.w;
    float4 y = *(const float4*)&g_y[idx];
    float4 r;
    if (!LAST) r = *(const float4*)&g_r[idx];

    float dot = p.x * q.x + p.y * q.y + p.z * q.z + p.w * q.w;
    dot = warp_sum(dot);
    if ((tid & 31) == 0) sdot[w] = dot;
    __syncthreads();
    float alpha = rro / fmaxf((sdot[0] + sdot[1]) + (sdot[2] + sdot[3]), 1e-30f);

    if (LAST) {
        float os = g_oscale[b];
        float4 o;
        o.x = os * (y.x + alpha * p.x);
        o.y = os * (y.y + alpha * p.y);
        o.z = os * (y.z + alpha * p.z);
        o.w = os * (y.w + alpha * p.w);
        *(float4*)&out[idx] = o;
        return;
    }

    y.x += alpha * p.x; y.y += alpha * p.y;
    y.z += alpha * p.z; y.w += alpha * p.w;
    *(float4*)&g_y[idx] = y;
    r.x -= alpha * q.x; r.y -= alpha * q.y;
    r.z -= alpha * q.z; r.w -= alpha * q.w;
    *(float4*)&g_r[idx] = r;

    float rr_new = r.x * r.x + r.y * r.y + r.z * r.z + r.w * r.w;
    rr_new = warp_sum(rr_new);
    if ((tid & 31) == 0) srr[w] = rr_new;
    __syncthreads();
    rr_new = (srr[0] + srr[1]) + (srr[2] + srr[3]);
    float beta = rr_new / fmaxf(rro, 1e-30f);
    if (tid == 0) g_rr[b] = rr_new;

    float4 pn;
    pn.x = r.x + beta * p.x;
    pn.y = r.y + beta * p.y;
    pn.z = r.z + beta * p.z;
    pn.w = r.w + beta * p.w;
    *(float4*)&g_p[idx] = pn;

    __nv_bfloat162 h01, h23, l01, l23;
    h01.x = __float2bfloat16(pn.x);
    h01.y = __float2bfloat16(pn.y);
    h23.x = __float2bfloat16(pn.z);
    h23.y = __float2bfloat16(pn.w);
    l01.x = __float2bfloat16(pn.x - __bfloat162float(h01.x));
    l01.y = __float2bfloat16(pn.y - __bfloat162float(h01.y));
    l23.x = __float2bfloat16(pn.z - __bfloat162float(h23.x));
    l23.y = __float2bfloat16(pn.w - __bfloat162float(h23.y));
    *(__nv_bfloat162*)&g_p_hi[idx] = h01;
    *(__nv_bfloat162*)&g_p_hi[idx + 2] = h23;
    *(__nv_bfloat162*)&g_p_lo[idx] = l01;
    *(__nv_bfloat162*)&g_p_lo[idx + 2] = l23;
}

// ---------------------------------------------------------------------------
extern "C" void kernel_launch(void* const* d_in, const int* in_sizes, int n_in,
                              void* d_out, int out_size) {
    const float* x = (const float*)d_in[0];
    const float* t = (const float*)d_in[1];
    const float* mu = (const float*)d_in[2];
    const float* cov = (const float*)d_in[3];
    float* out = (float*)d_out;

    const int gemm_smem = 4 * TILE_ELEMS * (int)sizeof(__nv_bfloat16);  // ~70 KB
    cudaFuncSetAttribute(gemm_mma_kernel,
                         cudaFuncAttributeMaxDynamicSharedMemorySize, gemm_smem);

    setup_kernel<<<576, 256>>>(x, t, mu, cov);
    dim3 ggrid(DD / 64, BATCH / 64, SPLITK);  // (8, 8, 4) = 256 CTAs
    for (int it = 0; it < NITER - 1; it++) {
        gemm_mma_kernel<<<ggrid, 128, gemm_smem>>>();
        cg_update_kernel<false><<<BATCH, 128>>>(nullptr);
    }
    gemm_mma_kernel<<<ggrid, 128, gemm_smem>>>();
    cg_update_kernel<true><<<BATCH, 128>>>(out);
}